// round 1
// baseline (speedup 1.0000x reference)
#include <cuda_runtime.h>

// TEPRNN2: fc1(1->4,tanh) -> LSTM(4->64) over S=256 -> fc2(64->1), B=4096.
// One hidden unit per thread, 8 batches per thread, f32x2 packed FMA mainloop.

#define S_LEN   256
#define HID     64
#define BPB     32      // batches per block
#define RB      8       // batches per group (per thread)
#define THREADS 256     // 4 groups x 64 threads
#define WSM_STRIDE 260  // 256 + 4 pad floats per unit row (bank-conflict-free LDS.128)

typedef unsigned long long ull;

__device__ __forceinline__ void ffma2(ull &d, ull a, ull b) {
    asm volatile("fma.rn.f32x2 %0, %1, %2, %3;" : "=l"(d) : "l"(a), "l"(b), "l"(d));
}
__device__ __forceinline__ float2 unpk(ull v) {
    float2 r;
    asm("mov.b64 {%0, %1}, %2;" : "=f"(r.x), "=f"(r.y) : "l"(v));
    return r;
}
__device__ __forceinline__ float sigm_f(float x) {
    x = fminf(fmaxf(x, -30.f), 30.f);
    float e = __expf(-x);
    return __fdividef(1.f, 1.f + e);
}
__device__ __forceinline__ float tanh_f(float x) {
    x = fminf(fmaxf(x, -15.f), 15.f);
    float e = __expf(-2.f * x);
    return __fdividef(1.f - e, 1.f + e);
}

// Shared layout (floats):
//   Wsm   : [64][260]                      = 16640
//   group : 4 x { hsm[2][8][64]=1024, fc1[8][4]=32 } = 4224
//   w2sm  : 64
#define SMEM_FLOATS (16640 + 4 * 1056 + 64)

extern __shared__ float smem[];

__global__ __launch_bounds__(THREADS, 1)
void teprnn2_kernel(const float* __restrict__ x,
                    const float* __restrict__ W1,
                    const float* __restrict__ b1,
                    const float* __restrict__ W_ih,
                    const float* __restrict__ W_hh,
                    const float* __restrict__ b_ih,
                    const float* __restrict__ b_hh,
                    const float* __restrict__ W2,
                    const float* __restrict__ b2,
                    float* __restrict__ out)
{
    float* Wsm   = smem;
    float* gbase = smem + 16640;
    float* w2sm  = smem + 16640 + 4 * 1056;

    const int tid  = threadIdx.x;
    const int grp  = tid >> 6;
    const int gtid = tid & 63;
    const int u    = gtid;

    float* hsm  = gbase + grp * 1056;        // [2][8][64]
    float* fc1g = hsm + 1024;                // [8][4]

    // ---- Load W_hh reordered: Wsm[u][j*64 + k] = W_hh[(j*64+u)*64 + k] ----
    for (int i = tid; i < 16384; i += THREADS) {
        int row = i >> 6;        // gate row g = j*64 + u
        int k   = i & 63;
        Wsm[(row & 63) * WSM_STRIDE + (row >> 6) * 64 + k] = W_hh[i];
    }
    if (tid < 64) w2sm[tid] = W2[tid];

    // zero h buffer 0 for this group
    #pragma unroll
    for (int b = 0; b < RB; ++b) hsm[b * 64 + u] = 0.f;

    // per-thread W_ih rows + combined bias for its unit
    float wih[4][4], bias[4];
    #pragma unroll
    for (int j = 0; j < 4; ++j) {
        int row = j * 64 + u;
        #pragma unroll
        for (int i = 0; i < 4; ++i) wih[j][i] = W_ih[row * 4 + i];
        bias[j] = b_ih[row] + b_hh[row];
    }

    // fc1 duty: gtid<32 -> (batch = gtid>>2, feature i = gtid&3)
    const int bbase = blockIdx.x * BPB + grp * RB;
    float w1r = 0.f, b1r = 0.f;
    const float* xrow = x;  // valid base; only used when gtid<32
    if (gtid < 32) {
        int i = gtid & 3;
        w1r  = W1[i];
        b1r  = b1[i];
        xrow = x + (size_t)(bbase + (gtid >> 2)) * S_LEN;
    }

    float c[RB];
    #pragma unroll
    for (int b = 0; b < RB; ++b) c[b] = 0.f;

    const float* Wu = Wsm + u * WSM_STRIDE;
    __syncthreads();

    for (int s = 0; s < S_LEN; ++s) {
        // prefetch x for this step's fc1 (used after the k-loop)
        float xv = 0.f;
        if (gtid < 32) xv = __ldg(xrow + s);

        const int    rbuf = s & 1;
        const float* hb   = hsm + rbuf * 512;

        ull acc[4][RB];
        #pragma unroll
        for (int j = 0; j < 4; ++j)
            #pragma unroll
            for (int b = 0; b < RB; ++b) acc[j][b] = 0ULL;

        // ---- recurrent matvec: gates += W_hh[:,k] * h[k], f32x2 over k-pairs ----
        #pragma unroll
        for (int k4 = 0; k4 < 16; ++k4) {
            ulonglong2 w[4];
            #pragma unroll
            for (int j = 0; j < 4; ++j)
                w[j] = *(const ulonglong2*)(Wu + j * 64 + k4 * 4);
            #pragma unroll
            for (int b = 0; b < RB; ++b) {
                ulonglong2 hv = *(const ulonglong2*)(hb + b * 64 + k4 * 4);
                #pragma unroll
                for (int j = 0; j < 4; ++j) {
                    ffma2(acc[j][b], w[j].x, hv.x);
                    ffma2(acc[j][b], w[j].y, hv.y);
                }
            }
        }

        // fc1 for this step (32 threads per group)
        if (gtid < 32) {
            float t = tanh_f(fmaf(xv, w1r, b1r));
            fc1g[(gtid >> 2) * 4 + (gtid & 3)] = t;
        }
        __syncthreads();

        // ---- gate activations + state update ----
        float* hw = hsm + (1 - rbuf) * 512;
        #pragma unroll
        for (int b = 0; b < RB; ++b) {
            float4 f4 = *(const float4*)(fc1g + b * 4);
            float pre[4];
            #pragma unroll
            for (int j = 0; j < 4; ++j) {
                float2 p = unpk(acc[j][b]);
                pre[j] = p.x + p.y + bias[j]
                       + wih[j][0] * f4.x + wih[j][1] * f4.y
                       + wih[j][2] * f4.z + wih[j][3] * f4.w;
            }
            float ig = sigm_f(pre[0]);
            float fg = sigm_f(pre[1]);
            float gg = tanh_f(pre[2]);
            float og = sigm_f(pre[3]);
            c[b] = fg * c[b] + ig * gg;
            hw[b * 64 + u] = og * tanh_f(c[b]);
        }
        __syncthreads();
    }

    // final h lives in buffer 0 (written by s=255: wbuf = 1-(255&1) = 0)
    if (gtid < 8) {
        const float* hf = hsm + gtid * 64;
        float sum = 0.f;
        #pragma unroll
        for (int k = 0; k < 64; ++k) sum = fmaf(w2sm[k], hf[k], sum);
        out[bbase + gtid] = sum + b2[0];
    }
}

extern "C" void kernel_launch(void* const* d_in, const int* in_sizes, int n_in,
                              void* d_out, int out_size)
{
    const float* x    = (const float*)d_in[0];
    const float* W1   = (const float*)d_in[1];
    const float* b1   = (const float*)d_in[2];
    const float* W_ih = (const float*)d_in[3];
    const float* W_hh = (const float*)d_in[4];
    const float* b_ih = (const float*)d_in[5];
    const float* b_hh = (const float*)d_in[6];
    const float* W2   = (const float*)d_in[7];
    const float* b2   = (const float*)d_in[8];
    float* out = (float*)d_out;

    const int smem_bytes = SMEM_FLOATS * (int)sizeof(float);
    cudaFuncSetAttribute(teprnn2_kernel,
                         cudaFuncAttributeMaxDynamicSharedMemorySize, smem_bytes);

    teprnn2_kernel<<<4096 / BPB, THREADS, smem_bytes>>>(
        x, W1, b1, W_ih, W_hh, b_ih, b_hh, W2, b2, out);
}

// round 2
// speedup vs baseline: 1.0673x; 1.0673x over previous
#include <cuda_runtime.h>

// TEPRNN2: fc1(1->4,tanh) -> LSTM(4->64) over S=256 -> fc2(64->1), B=4096.
// One hidden unit per thread, 8 batches per 2-warp group, f32x2 FMA mainloop.
// Round 2: group-local named barriers (desynchronized groups keep fma pipe fed)
//          + chunked fc1 precompute (1 barrier/step instead of 2).

#define S_LEN   256
#define HID     64
#define BPB     32      // batches per block
#define RB      8       // batches per group
#define THREADS 256     // 4 groups x 64 threads
#define CHUNK   16      // fc1 precompute chunk (steps)
#define WSM_STRIDE 260  // 256 + 4 pad floats (bank-conflict-free LDS.128)

typedef unsigned long long ull;

__device__ __forceinline__ void ffma2(ull &d, ull a, ull b) {
    asm volatile("fma.rn.f32x2 %0, %1, %2, %3;" : "=l"(d) : "l"(a), "l"(b), "l"(d));
}
__device__ __forceinline__ float2 unpk(ull v) {
    float2 r;
    asm("mov.b64 {%0, %1}, %2;" : "=f"(r.x), "=f"(r.y) : "l"(v));
    return r;
}
__device__ __forceinline__ float sigm_f(float x) {
    x = fminf(fmaxf(x, -30.f), 30.f);
    float e = __expf(-x);
    return __fdividef(1.f, 1.f + e);
}
__device__ __forceinline__ float tanh_f(float x) {
    x = fminf(fmaxf(x, -15.f), 15.f);
    float e = __expf(-2.f * x);
    return __fdividef(1.f - e, 1.f + e);
}
__device__ __forceinline__ void barg(int grp) {
    asm volatile("bar.sync %0, 64;" :: "r"(grp + 1) : "memory");
}

// Shared layout (floats):
//   Wsm   : [64][260]                               = 16640
//   group : 4 x { hsm[2][8][64]=1024, fc1c[8][16][4]=512 } = 6144
//   w2sm  : 64
#define GRP_FLOATS 1536
#define SMEM_FLOATS (16640 + 4 * GRP_FLOATS + 64)

extern __shared__ float smem[];

__global__ __launch_bounds__(THREADS, 1)
void teprnn2_kernel(const float* __restrict__ x,
                    const float* __restrict__ W1,
                    const float* __restrict__ b1,
                    const float* __restrict__ W_ih,
                    const float* __restrict__ W_hh,
                    const float* __restrict__ b_ih,
                    const float* __restrict__ b_hh,
                    const float* __restrict__ W2,
                    const float* __restrict__ b2,
                    float* __restrict__ out)
{
    float* Wsm   = smem;
    float* gbase = smem + 16640;
    float* w2sm  = smem + 16640 + 4 * GRP_FLOATS;

    const int tid  = threadIdx.x;
    const int grp  = tid >> 6;
    const int gtid = tid & 63;
    const int u    = gtid;

    float* hsm  = gbase + grp * GRP_FLOATS;   // [2][8][64]
    float* fc1c = hsm + 1024;                 // [8][16][4]

    // ---- Load W_hh reordered: Wsm[u][j*64 + k] = W_hh[(j*64+u)*64 + k] ----
    for (int i = tid; i < 16384; i += THREADS) {
        int row = i >> 6;
        int k   = i & 63;
        Wsm[(row & 63) * WSM_STRIDE + (row >> 6) * 64 + k] = W_hh[i];
    }
    if (tid < 64) w2sm[tid] = W2[tid];

    // zero h buffer 0 for this group
    #pragma unroll
    for (int b = 0; b < RB; ++b) hsm[b * 64 + u] = 0.f;

    // per-thread W_ih rows + combined bias for its unit
    float wih[4][4], bias[4];
    #pragma unroll
    for (int j = 0; j < 4; ++j) {
        int row = j * 64 + u;
        #pragma unroll
        for (int i = 0; i < 4; ++i) wih[j][i] = W_ih[row * 4 + i];
        bias[j] = b_ih[row] + b_hh[row];
    }

    // fc1 params (all 4 features in registers, every thread)
    float w1v[4], b1v[4];
    #pragma unroll
    for (int i = 0; i < 4; ++i) { w1v[i] = W1[i]; b1v[i] = b1[i]; }

    const int bbase = blockIdx.x * BPB + grp * RB;

    float c[RB];
    #pragma unroll
    for (int b = 0; b < RB; ++b) c[b] = 0.f;

    const float* Wu = Wsm + u * WSM_STRIDE;
    __syncthreads();   // Wsm + w2sm + h init visible to all groups

    for (int s0 = 0; s0 < S_LEN; s0 += CHUNK) {
        // ---- fc1 chunk: fc1c[b][si][0..3] = tanh(x[b][s0+si]*W1 + b1) ----
        // 8b x 16si = 128 float4 slots; 64 threads x 2 slots each.
        #pragma unroll
        for (int q = 0; q < 2; ++q) {
            int p  = gtid * 2 + q;
            int b  = p >> 4;
            int si = p & 15;
            float xv = __ldg(x + (size_t)(bbase + b) * S_LEN + s0 + si);
            float4 t;
            t.x = tanh_f(fmaf(xv, w1v[0], b1v[0]));
            t.y = tanh_f(fmaf(xv, w1v[1], b1v[1]));
            t.z = tanh_f(fmaf(xv, w1v[2], b1v[2]));
            t.w = tanh_f(fmaf(xv, w1v[3], b1v[3]));
            *(float4*)(fc1c + p * 4) = t;
        }
        barg(grp);   // fc1 chunk visible to group

        #pragma unroll 2
        for (int si = 0; si < CHUNK; ++si) {
            const int    rbuf = si & 1;       // s0 is even multiple of CHUNK
            const float* hb   = hsm + rbuf * 512;

            ull acc[4][RB];
            #pragma unroll
            for (int j = 0; j < 4; ++j)
                #pragma unroll
                for (int b = 0; b < RB; ++b) acc[j][b] = 0ULL;

            // ---- recurrent matvec: gates += W_hh[:,k] * h[k] (f32x2) ----
            #pragma unroll
            for (int k4 = 0; k4 < 16; ++k4) {
                ulonglong2 w[4];
                #pragma unroll
                for (int j = 0; j < 4; ++j)
                    w[j] = *(const ulonglong2*)(Wu + j * 64 + k4 * 4);
                #pragma unroll
                for (int b = 0; b < RB; ++b) {
                    ulonglong2 hv = *(const ulonglong2*)(hb + b * 64 + k4 * 4);
                    #pragma unroll
                    for (int j = 0; j < 4; ++j) {
                        ffma2(acc[j][b], w[j].x, hv.x);
                        ffma2(acc[j][b], w[j].y, hv.y);
                    }
                }
            }

            // ---- gate activations + state update ----
            float* hw = hsm + (1 - rbuf) * 512;
            #pragma unroll
            for (int b = 0; b < RB; ++b) {
                float4 f4 = *(const float4*)(fc1c + (b * CHUNK + si) * 4);
                float pre[4];
                #pragma unroll
                for (int j = 0; j < 4; ++j) {
                    float2 p = unpk(acc[j][b]);
                    pre[j] = p.x + p.y + bias[j]
                           + wih[j][0] * f4.x + wih[j][1] * f4.y
                           + wih[j][2] * f4.z + wih[j][3] * f4.w;
                }
                float ig = sigm_f(pre[0]);
                float fg = sigm_f(pre[1]);
                float gg = tanh_f(pre[2]);
                float og = sigm_f(pre[3]);
                c[b] = fg * c[b] + ig * gg;
                hw[b * 64 + u] = og * tanh_f(c[b]);
            }
            barg(grp);   // h(next) visible to group
        }
    }

    // final h in buffer 0 (step 255 wrote 1-(255&1) = 0)
    if (gtid < RB) {
        const float* hf = hsm + gtid * 64;
        ull s2 = 0ULL;
        #pragma unroll
        for (int k = 0; k < 32; ++k)
            ffma2(s2, *(const ull*)(w2sm + k * 2), *(const ull*)(hf + k * 2));
        float2 sp = unpk(s2);
        out[bbase + gtid] = sp.x + sp.y + b2[0];
    }
}

extern "C" void kernel_launch(void* const* d_in, const int* in_sizes, int n_in,
                              void* d_out, int out_size)
{
    const float* x    = (const float*)d_in[0];
    const float* W1   = (const float*)d_in[1];
    const float* b1   = (const float*)d_in[2];
    const float* W_ih = (const float*)d_in[3];
    const float* W_hh = (const float*)d_in[4];
    const float* b_ih = (const float*)d_in[5];
    const float* b_hh = (const float*)d_in[6];
    const float* W2   = (const float*)d_in[7];
    const float* b2   = (const float*)d_in[8];
    float* out = (float*)d_out;

    const int smem_bytes = SMEM_FLOATS * (int)sizeof(float);
    cudaFuncSetAttribute(teprnn2_kernel,
                         cudaFuncAttributeMaxDynamicSharedMemorySize, smem_bytes);

    teprnn2_kernel<<<4096 / BPB, THREADS, smem_bytes>>>(
        x, W1, b1, W_ih, W_hh, b_ih, b_hh, W2, b2, out);
}